// round 6
// baseline (speedup 1.0000x reference)
#include <cuda_runtime.h>
#include <cstdint>

using ull = unsigned long long;

#define THREADS 256
#define TILE    512            // 2 edges per thread, one f32x2 pack
#define HID     10
#define NOUT    19
#define ST_FLOATS (TILE * NOUT)          // 9728 floats
#define ST_BYTES  (ST_FLOATS * 4)        // 38912 bytes

// ---------- packed f32x2 helpers ----------
__device__ __forceinline__ ull pack2(float lo, float hi) {
    ull r; asm("mov.b64 %0, {%1, %2};" : "=l"(r) : "f"(lo), "f"(hi)); return r;
}
__device__ __forceinline__ void unpack2(ull v, float& lo, float& hi) {
    asm("mov.b64 {%0, %1}, %2;" : "=f"(lo), "=f"(hi) : "l"(v));
}
__device__ __forceinline__ ull ffma2(ull a, ull b, ull c) {
    ull d; asm("fma.rn.f32x2 %0, %1, %2, %3;" : "=l"(d) : "l"(a), "l"(b), "l"(c)); return d;
}
__device__ __forceinline__ ull add2(ull a, ull b) {
    ull d; asm("add.rn.f32x2 %0, %1, %2;" : "=l"(d) : "l"(a), "l"(b)); return d;
}
__device__ __forceinline__ ull relu2(ull a) {
    float lo, hi; unpack2(a, lo, hi);
    return pack2(fmaxf(lo, 0.0f), fmaxf(hi, 0.0f));
}

__global__ __launch_bounds__(THREADS, 3)
void edge_mlp_kernel(const float* __restrict__ src,
                     const float* __restrict__ dest,
                     const float* __restrict__ ea,
                     const float* __restrict__ u,
                     const int* __restrict__ batch,  // int32 graph ids
                     const float* __restrict__ W1,   // (4,10) row-major
                     const float* __restrict__ b1,   // (10)
                     const float* __restrict__ W2,   // (10,19) row-major
                     const float* __restrict__ b2,   // (19)
                     float* __restrict__ out,        // (E,19)
                     int E, int B, int nTiles)
{
    extern __shared__ __align__(16) char smem[];
    float* st = (float*)smem;                               // [512*19] staging
    float* su = (float*)(smem + ST_BYTES);                  // [B] u table
    const int ub = (B * 4 + 15) & ~15;
    ull* W1p = (ull*)(smem + ST_BYTES + ub);                // [40]  (w,w) pairs: [j][r]
    ull* b1p = W1p + 40;                                    // [10]
    ull* W2p = b1p + 10;                                    // [190] [k][j]
    ull* b2p = W2p + 190;                                   // [19]

    const int tid = threadIdx.x;
    const int Bm1 = B - 1;

    // ---- one-time per-block init: u table + duplicated-pair weights ----
    for (int i = tid; i < B; i += THREADS) su[i] = u[i];
    if (tid < 40) {                       // W1p[j*4+r] = (W1[r][j], W1[r][j])
        int j = tid >> 2, r = tid & 3;
        float w = W1[r * 10 + j];
        W1p[tid] = pack2(w, w);
    }
    if (tid < 10) { float v = b1[tid]; b1p[tid] = pack2(v, v); }
    if (tid < 190) {                      // W2p[k*10+j] = (W2[j][k], W2[j][k])
        int k = tid / 10, j = tid - k * 10;
        float w = W2[j * NOUT + k];
        W2p[tid] = pack2(w, w);
    }
    if (tid < NOUT) { float v = b2[tid]; b2p[tid] = pack2(v, v); }
    __syncthreads();

    const ulonglong2* W1v = (const ulonglong2*)W1p;

    for (int tile = blockIdx.x; tile < nTiles; tile += gridDim.x) {
        const int base = tile * TILE;
        const bool full = (base + TILE) <= E;

        if (full) {
            const int g0 = base + tid;
            const int g1 = g0 + THREADS;
            // coalesced loads, two edges per thread
            float s0 = src[g0],  s1 = src[g1];
            float d0 = dest[g0], d1 = dest[g1];
            float a0 = ea[g0],   a1 = ea[g1];
            int   i0 = batch[g0], i1 = batch[g1];
            i0 = min(max(i0, 0), Bm1);
            i1 = min(max(i1, 0), Bm1);
            ull S = pack2(s0, s1);
            ull D = pack2(d0, d1);
            ull A = pack2(a0, a1);
            ull U = pack2(su[i0], su[i1]);

            // ---- stage 1: h = relu(x @ W1 + b1) ----
            ull h[HID];
            #pragma unroll
            for (int j = 0; j < HID; j++) {
                ulonglong2 w01 = W1v[j * 2 + 0];   // (W1[0][j]),(W1[1][j]) pairs
                ulonglong2 w23 = W1v[j * 2 + 1];   // (W1[2][j]),(W1[3][j]) pairs
                ull acc = ffma2(S, w01.x, b1p[j]);
                acc = ffma2(D, w01.y, acc);
                acc = ffma2(A, w23.x, acc);
                acc = ffma2(U, w23.y, acc);
                h[j] = relu2(acc);
            }

            // ---- stage 2: out = h @ W2 + b2 ; even/odd dual chains, fully unrolled ----
            #pragma unroll
            for (int k = 0; k < NOUT; k++) {
                const ulonglong2* wr = (const ulonglong2*)(W2p + k * HID);
                ulonglong2 w0 = wr[0], w1 = wr[1], w2 = wr[2], w3 = wr[3], w4 = wr[4];
                ull accA = ffma2(h[0], w0.x, b2p[k]);
                ull accB = ffma2(h[1], w0.y, 0ULL);     // (0.0f,0.0f)
                accA = ffma2(h[2], w1.x, accA);
                accB = ffma2(h[3], w1.y, accB);
                accA = ffma2(h[4], w2.x, accA);
                accB = ffma2(h[5], w2.y, accB);
                accA = ffma2(h[6], w3.x, accA);
                accB = ffma2(h[7], w3.y, accB);
                accA = ffma2(h[8], w4.x, accA);
                accB = ffma2(h[9], w4.y, accB);
                ull acc = add2(accA, accB);
                float lo, hi; unpack2(acc, lo, hi);
                st[tid * NOUT + k]               = lo;   // stride 19: conflict-free
                st[(tid + THREADS) * NOUT + k]   = hi;
            }
            __syncthreads();

            // ---- coalesced float4 flush: 512*19 floats = 2432 float4 ----
            float4* o4 = (float4*)(out + (size_t)base * NOUT);
            const float4* s4 = (const float4*)st;
            #pragma unroll
            for (int q = 0; q < ST_FLOATS / 4 / THREADS + 1; q++) {
                int idx = q * THREADS + tid;
                if (idx < ST_FLOATS / 4) o4[idx] = s4[idx];
            }
            __syncthreads();
        } else {
            // -------- tail tile (never hit for E % 512 == 0, kept for safety) ----
            const float* W1f = (const float*)W1p;  // lo halves of packed pairs
            const float* b1f = (const float*)b1p;
            const float* W2f = (const float*)W2p;
            const float* b2f = (const float*)b2p;
            #pragma unroll
            for (int half = 0; half < 2; half++) {
                int row = tid + half * THREADS;
                int g = base + row;
                if (g < E) {
                    float s = src[g], d = dest[g], a = ea[g];
                    int bi = min(max(batch[g], 0), Bm1);
                    float uu = su[bi];
                    float h[HID];
                    #pragma unroll
                    for (int j = 0; j < HID; j++) {
                        float acc = b1f[j * 2];
                        acc = fmaf(s,  W1f[(j * 4 + 0) * 2], acc);
                        acc = fmaf(d,  W1f[(j * 4 + 1) * 2], acc);
                        acc = fmaf(a,  W1f[(j * 4 + 2) * 2], acc);
                        acc = fmaf(uu, W1f[(j * 4 + 3) * 2], acc);
                        h[j] = fmaxf(acc, 0.0f);
                    }
                    #pragma unroll
                    for (int k = 0; k < NOUT; k++) {
                        float acc = b2f[k * 2];
                        #pragma unroll
                        for (int j = 0; j < HID; j++)
                            acc = fmaf(h[j], W2f[(k * HID + j) * 2], acc);
                        st[row * NOUT + k] = acc;
                    }
                }
            }
            __syncthreads();
            int ve = E - base; if (ve > TILE) ve = TILE;
            size_t obase = (size_t)base * NOUT;
            for (int q = tid; q < ve * NOUT; q += THREADS) out[obase + q] = st[q];
            __syncthreads();
        }
    }
}

extern "C" void kernel_launch(void* const* d_in, const int* in_sizes, int n_in,
                              void* d_out, int out_size)
{
    const float* src   = (const float*)d_in[0];
    const float* dest  = (const float*)d_in[1];
    const float* ea    = (const float*)d_in[2];
    const float* u     = (const float*)d_in[3];
    const int*   batch = (const int*)d_in[4];      // int32
    const float* W1    = (const float*)d_in[5];
    const float* b1    = (const float*)d_in[6];
    const float* W2    = (const float*)d_in[7];
    const float* b2    = (const float*)d_in[8];
    float* out = (float*)d_out;

    const int E = in_sizes[0];
    const int B = in_sizes[3];
    const int nTiles = (E + TILE - 1) / TILE;

    const int ub = (B * 4 + 15) & ~15;
    const int smemBytes = ST_BYTES + ub + (40 + 10 + 190 + 19) * 8 + 16;

    cudaFuncSetAttribute(edge_mlp_kernel,
                         cudaFuncAttributeMaxDynamicSharedMemorySize, smemBytes);

    int grid = nTiles < 444 ? nTiles : 444;   // 3 CTAs/SM resident, grid-stride
    if (grid < 1) grid = 1;

    edge_mlp_kernel<<<grid, THREADS, smemBytes>>>(
        src, dest, ea, u, batch, W1, b1, W2, b2, out, E, B, nTiles);
}

// round 7
// speedup vs baseline: 1.2397x; 1.2397x over previous
#include <cuda_runtime.h>
#include <cstdint>

using ull = unsigned long long;

#define THREADS 256
#define PACKS   2              // f32x2 packs per thread (2 edges each) -> 4 edges/thread
#define TILE    1024           // THREADS * 2 * PACKS
#define HID     10
#define NOUT    19
#define ST_FLOATS (TILE * NOUT)          // 19456 floats
#define ST_BYTES  (ST_FLOATS * 4)        // 77824 bytes

// ---------- packed f32x2 helpers ----------
__device__ __forceinline__ ull pack2(float lo, float hi) {
    ull r; asm("mov.b64 %0, {%1, %2};" : "=l"(r) : "f"(lo), "f"(hi)); return r;
}
__device__ __forceinline__ void unpack2(ull v, float& lo, float& hi) {
    asm("mov.b64 {%0, %1}, %2;" : "=f"(lo), "=f"(hi) : "l"(v));
}
__device__ __forceinline__ ull ffma2(ull a, ull b, ull c) {
    ull d; asm("fma.rn.f32x2 %0, %1, %2, %3;" : "=l"(d) : "l"(a), "l"(b), "l"(c)); return d;
}
__device__ __forceinline__ ull add2(ull a, ull b) {
    ull d; asm("add.rn.f32x2 %0, %1, %2;" : "=l"(d) : "l"(a), "l"(b)); return d;
}
__device__ __forceinline__ ull relu2(ull a) {
    float lo, hi; unpack2(a, lo, hi);
    return pack2(fmaxf(lo, 0.0f), fmaxf(hi, 0.0f));
}

__global__ __launch_bounds__(THREADS, 2)
void edge_mlp_kernel(const float* __restrict__ src,
                     const float* __restrict__ dest,
                     const float* __restrict__ ea,
                     const float* __restrict__ u,
                     const int* __restrict__ batch,  // int32 graph ids
                     const float* __restrict__ W1,   // (4,10) row-major
                     const float* __restrict__ b1,   // (10)
                     const float* __restrict__ W2,   // (10,19) row-major
                     const float* __restrict__ b2,   // (19)
                     float* __restrict__ out,        // (E,19)
                     int E, int B, int nTiles)
{
    extern __shared__ __align__(16) char smem[];
    float* st = (float*)smem;                               // [1024*19] staging
    float* su = (float*)(smem + ST_BYTES);                  // [B] u table
    const int ub = (B * 4 + 15) & ~15;
    ull* W1p = (ull*)(smem + ST_BYTES + ub);                // [40]  (w,w) pairs: [j][r]
    ull* b1p = W1p + 40;                                    // [10]
    ull* W2p = b1p + 10;                                    // [190] [k][j]
    ull* b2p = W2p + 190;                                   // [19]

    const int tid = threadIdx.x;
    const int Bm1 = B - 1;

    // ---- one-time per-block init: u table + duplicated-pair weights ----
    for (int i = tid; i < B; i += THREADS) su[i] = u[i];
    if (tid < 40) {                       // W1p[j*4+r] = (W1[r][j], W1[r][j])
        int j = tid >> 2, r = tid & 3;
        float w = W1[r * 10 + j];
        W1p[tid] = pack2(w, w);
    }
    if (tid < 10) { float v = b1[tid]; b1p[tid] = pack2(v, v); }
    if (tid < 190) {                      // W2p[k*10+j] = (W2[j][k], W2[j][k])
        int k = tid / 10, j = tid - k * 10;
        float w = W2[j * NOUT + k];
        W2p[tid] = pack2(w, w);
    }
    if (tid < NOUT) { float v = b2[tid]; b2p[tid] = pack2(v, v); }
    __syncthreads();

    const ulonglong2* W1v = (const ulonglong2*)W1p;
    const int stride = gridDim.x;

    // ---- software pipeline: raw input regs for the *current* tile ----
    float cs[PACKS][2], cd[PACKS][2], ca[PACKS][2];
    int   ci[PACKS][2];

    int tile = blockIdx.x;
    bool curFull = (tile < nTiles) && ((tile * TILE + TILE) <= E);
    if (curFull) {
        const int base = tile * TILE;
        #pragma unroll
        for (int c = 0; c < PACKS; c++) {
            const int g0 = base + c * (2 * THREADS) + tid;
            const int g1 = g0 + THREADS;
            cs[c][0] = src[g0];  cs[c][1] = src[g1];
            cd[c][0] = dest[g0]; cd[c][1] = dest[g1];
            ca[c][0] = ea[g0];   ca[c][1] = ea[g1];
            ci[c][0] = batch[g0]; ci[c][1] = batch[g1];
        }
    }

    for (; tile < nTiles; tile += stride) {
        const int base = tile * TILE;
        const int nextTile = tile + stride;
        const bool nextFull = (nextTile < nTiles) && ((nextTile * TILE + TILE) <= E);

        if (curFull) {
            // ---- consume raw regs into packed operands (u gathered from smem now) ----
            ull S[PACKS], D[PACKS], A[PACKS], U[PACKS];
            #pragma unroll
            for (int c = 0; c < PACKS; c++) {
                int i0 = min(max(ci[c][0], 0), Bm1);
                int i1 = min(max(ci[c][1], 0), Bm1);
                S[c] = pack2(cs[c][0], cs[c][1]);
                D[c] = pack2(cd[c][0], cd[c][1]);
                A[c] = pack2(ca[c][0], ca[c][1]);
                U[c] = pack2(su[i0], su[i1]);
            }

            // ---- prefetch next tile's raw inputs (hidden under the MLP below) ----
            if (nextFull) {
                const int nbase = nextTile * TILE;
                #pragma unroll
                for (int c = 0; c < PACKS; c++) {
                    const int g0 = nbase + c * (2 * THREADS) + tid;
                    const int g1 = g0 + THREADS;
                    cs[c][0] = src[g0];  cs[c][1] = src[g1];
                    cd[c][0] = dest[g0]; cd[c][1] = dest[g1];
                    ca[c][0] = ea[g0];   ca[c][1] = ea[g1];
                    ci[c][0] = batch[g0]; ci[c][1] = batch[g1];
                }
            }

            // ---- stage 1: h = relu(x @ W1 + b1); weight loads shared over packs ----
            ull h[PACKS][HID];
            #pragma unroll
            for (int j = 0; j < HID; j++) {
                ulonglong2 w01 = W1v[j * 2 + 0];
                ulonglong2 w23 = W1v[j * 2 + 1];
                ull bj = b1p[j];
                #pragma unroll
                for (int c = 0; c < PACKS; c++) {
                    ull acc = ffma2(S[c], w01.x, bj);
                    acc = ffma2(D[c], w01.y, acc);
                    acc = ffma2(A[c], w23.x, acc);
                    acc = ffma2(U[c], w23.y, acc);
                    h[c][j] = relu2(acc);
                }
            }

            // ---- stage 2: out = h @ W2 + b2; even/odd split accumulators ----
            for (int k = 0; k < NOUT; k++) {
                const ulonglong2* wr = (const ulonglong2*)(W2p + k * HID);
                ulonglong2 w0 = wr[0], w1 = wr[1], w2 = wr[2], w3 = wr[3], w4 = wr[4];
                ull bk = b2p[k];
                #pragma unroll
                for (int c = 0; c < PACKS; c++) {
                    ull accA = ffma2(h[c][0], w0.x, bk);
                    ull accB = ffma2(h[c][1], w0.y, 0ULL);
                    accA = ffma2(h[c][2], w1.x, accA);
                    accB = ffma2(h[c][3], w1.y, accB);
                    accA = ffma2(h[c][4], w2.x, accA);
                    accB = ffma2(h[c][5], w2.y, accB);
                    accA = ffma2(h[c][6], w3.x, accA);
                    accB = ffma2(h[c][7], w3.y, accB);
                    accA = ffma2(h[c][8], w4.x, accA);
                    accB = ffma2(h[c][9], w4.y, accB);
                    ull acc = add2(accA, accB);
                    float lo, hi; unpack2(acc, lo, hi);
                    const int row0 = c * (2 * THREADS) + tid;
                    st[row0 * NOUT + k]             = lo;
                    st[(row0 + THREADS) * NOUT + k] = hi;
                }
            }
            __syncthreads();

            // ---- coalesced float4 flush: 1024*19 floats = 4864 float4 ----
            float4* o4 = (float4*)(out + (size_t)base * NOUT);
            const float4* s4 = (const float4*)st;
            #pragma unroll
            for (int q = 0; q < ST_FLOATS / 4 / THREADS; q++)
                o4[q * THREADS + tid] = s4[q * THREADS + tid];
            __syncthreads();
        } else {
            // -------- tail tile (E % 1024 edges); loads its own inputs --------
            const float* W1f = (const float*)W1p;
            const float* b1f = (const float*)b1p;
            const float* W2f = (const float*)W2p;
            const float* b2f = (const float*)b2p;
            #pragma unroll
            for (int q = 0; q < 2 * PACKS; q++) {
                int row = tid + q * THREADS;
                int g = base + row;
                if (g < E) {
                    float s = src[g], d = dest[g], a = ea[g];
                    int bi = min(max(batch[g], 0), Bm1);
                    float uu = su[bi];
                    float h[HID];
                    #pragma unroll
                    for (int j = 0; j < HID; j++) {
                        float acc = b1f[j * 2];
                        acc = fmaf(s,  W1f[(j * 4 + 0) * 2], acc);
                        acc = fmaf(d,  W1f[(j * 4 + 1) * 2], acc);
                        acc = fmaf(a,  W1f[(j * 4 + 2) * 2], acc);
                        acc = fmaf(uu, W1f[(j * 4 + 3) * 2], acc);
                        h[j] = fmaxf(acc, 0.0f);
                    }
                    #pragma unroll
                    for (int k = 0; k < NOUT; k++) {
                        float acc = b2f[k * 2];
                        #pragma unroll
                        for (int j = 0; j < HID; j++)
                            acc = fmaf(h[j], W2f[(k * HID + j) * 2], acc);
                        st[row * NOUT + k] = acc;
                    }
                }
            }
            __syncthreads();
            int ve = E - base; if (ve > TILE) ve = TILE;
            size_t obase = (size_t)base * NOUT;
            for (int q = tid; q < ve * NOUT; q += THREADS) out[obase + q] = st[q];
            __syncthreads();

            // refill pipeline for the next iteration (rarely taken path)
            if (nextFull) {
                const int nbase = nextTile * TILE;
                #pragma unroll
                for (int c = 0; c < PACKS; c++) {
                    const int g0 = nbase + c * (2 * THREADS) + tid;
                    const int g1 = g0 + THREADS;
                    cs[c][0] = src[g0];  cs[c][1] = src[g1];
                    cd[c][0] = dest[g0]; cd[c][1] = dest[g1];
                    ca[c][0] = ea[g0];   ca[c][1] = ea[g1];
                    ci[c][0] = batch[g0]; ci[c][1] = batch[g1];
                }
            }
        }
        curFull = nextFull;
    }
}

extern "C" void kernel_launch(void* const* d_in, const int* in_sizes, int n_in,
                              void* d_out, int out_size)
{
    const float* src   = (const float*)d_in[0];
    const float* dest  = (const float*)d_in[1];
    const float* ea    = (const float*)d_in[2];
    const float* u     = (const float*)d_in[3];
    const int*   batch = (const int*)d_in[4];      // int32
    const float* W1    = (const float*)d_in[5];
    const float* b1    = (const float*)d_in[6];
    const float* W2    = (const float*)d_in[7];
    const float* b2    = (const float*)d_in[8];
    float* out = (float*)d_out;

    const int E = in_sizes[0];
    const int B = in_sizes[3];
    const int nTiles = (E + TILE - 1) / TILE;

    const int ub = (B * 4 + 15) & ~15;
    const int smemBytes = ST_BYTES + ub + (40 + 10 + 190 + 19) * 8 + 16;

    cudaFuncSetAttribute(edge_mlp_kernel,
                         cudaFuncAttributeMaxDynamicSharedMemorySize, smemBytes);

    int grid = nTiles < 296 ? nTiles : 296;   // 2 CTAs/SM resident, grid-stride
    if (grid < 1) grid = 1;

    edge_mlp_kernel<<<grid, THREADS, smemBytes>>>(
        src, dest, ea, u, batch, W1, b1, W2, b2, out, E, B, nTiles);
}

// round 8
// speedup vs baseline: 1.5534x; 1.2530x over previous
#include <cuda_runtime.h>
#include <cstdint>

using ull = unsigned long long;

#define THREADS 256
#define PACKS   2              // f32x2 packs per thread (2 edges each) -> 4 edges/thread
#define TILE    1024           // THREADS * 2 * PACKS
#define HID     10
#define NOUT    19
#define ST_FLOATS (TILE * NOUT)          // 19456 floats
#define ST_BYTES  (ST_FLOATS * 4)        // 77824 bytes
#define NWT       259                    // 40 W1 + 10 b1 + 190 W2 + 19 b2 (packed pairs)

// packed weight bank: [0,40) W1p[j*4+r], [40,50) b1p, [50,240) W2p[k*10+j], [240,259) b2p
__device__   ull gWt[NWT];
__constant__ ull cWt[NWT];

// ---------- packed f32x2 helpers ----------
__device__ __forceinline__ ull pack2(float lo, float hi) {
    ull r; asm("mov.b64 %0, {%1, %2};" : "=l"(r) : "f"(lo), "f"(hi)); return r;
}
__device__ __forceinline__ void unpack2(ull v, float& lo, float& hi) {
    asm("mov.b64 {%0, %1}, %2;" : "=f"(lo), "=f"(hi) : "l"(v));
}
__device__ __forceinline__ ull ffma2(ull a, ull b, ull c) {
    ull d; asm("fma.rn.f32x2 %0, %1, %2, %3;" : "=l"(d) : "l"(a), "l"(b), "l"(c)); return d;
}
__device__ __forceinline__ ull add2(ull a, ull b) {
    ull d; asm("add.rn.f32x2 %0, %1, %2;" : "=l"(d) : "l"(a), "l"(b)); return d;
}
__device__ __forceinline__ ull relu2(ull a) {
    float lo, hi; unpack2(a, lo, hi);
    return pack2(fmaxf(lo, 0.0f), fmaxf(hi, 0.0f));
}

// ---- prep: pack duplicated (w,w) pairs into gWt (then D2D-copied to cWt) ----
__global__ void pack_weights_kernel(const float* __restrict__ W1,
                                    const float* __restrict__ b1,
                                    const float* __restrict__ W2,
                                    const float* __restrict__ b2)
{
    int t = threadIdx.x;
    if (t < 40) {                       // W1p[j*4+r] = (W1[r][j], W1[r][j])
        int j = t >> 2, r = t & 3;
        float w = W1[r * 10 + j];
        gWt[t] = pack2(w, w);
    } else if (t < 50) {
        float v = b1[t - 40];  gWt[t] = pack2(v, v);
    } else if (t < 240) {               // W2p[k*10+j] = (W2[j][k], W2[j][k])
        int q = t - 50; int k = q / 10, j = q - k * 10;
        float w = W2[j * NOUT + k];
        gWt[t] = pack2(w, w);
    } else if (t < NWT) {
        float v = b2[t - 240]; gWt[t] = pack2(v, v);
    }
}

__global__ __launch_bounds__(THREADS, 2)
void edge_mlp_kernel(const float* __restrict__ src,
                     const float* __restrict__ dest,
                     const float* __restrict__ ea,
                     const float* __restrict__ u,
                     const int* __restrict__ batch,  // int32 graph ids
                     float* __restrict__ out,        // (E,19)
                     int E, int B, int nTiles)
{
    extern __shared__ __align__(16) char smem[];
    float* st = (float*)smem;                               // [1024*19] staging
    float* su = (float*)(smem + ST_BYTES);                  // [B] u table

    const int tid = threadIdx.x;
    const int Bm1 = B - 1;

    for (int i = tid; i < B; i += THREADS) su[i] = u[i];
    __syncthreads();

    const int stride = gridDim.x;

    // ---- software pipeline: raw input regs for the *current* tile ----
    float cs[PACKS][2], cd[PACKS][2], ca[PACKS][2];
    int   ci[PACKS][2];

    int tile = blockIdx.x;
    bool curFull = (tile < nTiles) && ((tile * TILE + TILE) <= E);
    if (curFull) {
        const int base = tile * TILE;
        #pragma unroll
        for (int c = 0; c < PACKS; c++) {
            const int g0 = base + c * (2 * THREADS) + tid;
            const int g1 = g0 + THREADS;
            cs[c][0] = src[g0];  cs[c][1] = src[g1];
            cd[c][0] = dest[g0]; cd[c][1] = dest[g1];
            ca[c][0] = ea[g0];   ca[c][1] = ea[g1];
            ci[c][0] = batch[g0]; ci[c][1] = batch[g1];
        }
    }

    for (; tile < nTiles; tile += stride) {
        const int base = tile * TILE;
        const int nextTile = tile + stride;
        const bool nextFull = (nextTile < nTiles) && ((nextTile * TILE + TILE) <= E);

        if (curFull) {
            // ---- consume raw regs into packed operands (u gathered from smem now) ----
            ull S[PACKS], D[PACKS], A[PACKS], U[PACKS];
            #pragma unroll
            for (int c = 0; c < PACKS; c++) {
                int i0 = min(max(ci[c][0], 0), Bm1);
                int i1 = min(max(ci[c][1], 0), Bm1);
                S[c] = pack2(cs[c][0], cs[c][1]);
                D[c] = pack2(cd[c][0], cd[c][1]);
                A[c] = pack2(ca[c][0], ca[c][1]);
                U[c] = pack2(su[i0], su[i1]);
            }

            // ---- prefetch next tile's raw inputs (hidden under the MLP below) ----
            if (nextFull) {
                const int nbase = nextTile * TILE;
                #pragma unroll
                for (int c = 0; c < PACKS; c++) {
                    const int g0 = nbase + c * (2 * THREADS) + tid;
                    const int g1 = g0 + THREADS;
                    cs[c][0] = src[g0];  cs[c][1] = src[g1];
                    cd[c][0] = dest[g0]; cd[c][1] = dest[g1];
                    ca[c][0] = ea[g0];   ca[c][1] = ea[g1];
                    ci[c][0] = batch[g0]; ci[c][1] = batch[g1];
                }
            }

            // ---- stage 1: h = relu(x @ W1 + b1); weights from constant bank ----
            ull h[PACKS][HID];
            #pragma unroll
            for (int j = 0; j < HID; j++) {
                const ull w0 = cWt[j * 4 + 0];
                const ull w1 = cWt[j * 4 + 1];
                const ull w2 = cWt[j * 4 + 2];
                const ull w3 = cWt[j * 4 + 3];
                const ull bj = cWt[40 + j];
                #pragma unroll
                for (int c = 0; c < PACKS; c++) {
                    ull acc = ffma2(S[c], w0, bj);
                    acc = ffma2(D[c], w1, acc);
                    acc = ffma2(A[c], w2, acc);
                    acc = ffma2(U[c], w3, acc);
                    h[c][j] = relu2(acc);
                }
            }

            // ---- stage 2: out = h @ W2 + b2; constants, even/odd dual chains ----
            #pragma unroll
            for (int k = 0; k < NOUT; k++) {
                const ull wk0 = cWt[50 + k * 10 + 0];
                const ull wk1 = cWt[50 + k * 10 + 1];
                const ull wk2 = cWt[50 + k * 10 + 2];
                const ull wk3 = cWt[50 + k * 10 + 3];
                const ull wk4 = cWt[50 + k * 10 + 4];
                const ull wk5 = cWt[50 + k * 10 + 5];
                const ull wk6 = cWt[50 + k * 10 + 6];
                const ull wk7 = cWt[50 + k * 10 + 7];
                const ull wk8 = cWt[50 + k * 10 + 8];
                const ull wk9 = cWt[50 + k * 10 + 9];
                const ull bk  = cWt[240 + k];
                #pragma unroll
                for (int c = 0; c < PACKS; c++) {
                    ull accA = ffma2(h[c][0], wk0, bk);
                    ull accB = ffma2(h[c][1], wk1, 0ULL);
                    accA = ffma2(h[c][2], wk2, accA);
                    accB = ffma2(h[c][3], wk3, accB);
                    accA = ffma2(h[c][4], wk4, accA);
                    accB = ffma2(h[c][5], wk5, accB);
                    accA = ffma2(h[c][6], wk6, accA);
                    accB = ffma2(h[c][7], wk7, accB);
                    accA = ffma2(h[c][8], wk8, accA);
                    accB = ffma2(h[c][9], wk9, accB);
                    ull acc = add2(accA, accB);
                    float lo, hi; unpack2(acc, lo, hi);
                    const int row0 = c * (2 * THREADS) + tid;
                    st[row0 * NOUT + k]             = lo;   // stride 19: conflict-free
                    st[(row0 + THREADS) * NOUT + k] = hi;
                }
            }
            __syncthreads();

            // ---- coalesced float4 flush: 1024*19 floats = 4864 float4 ----
            float4* o4 = (float4*)(out + (size_t)base * NOUT);
            const float4* s4 = (const float4*)st;
            #pragma unroll
            for (int q = 0; q < ST_FLOATS / 4 / THREADS; q++)
                o4[q * THREADS + tid] = s4[q * THREADS + tid];
            __syncthreads();
        } else {
            // -------- tail tile (E % 1024 edges); loads its own inputs --------
            const float* cf = (const float*)cWt;   // lo halves of packed pairs
            #pragma unroll
            for (int q = 0; q < 2 * PACKS; q++) {
                int row = tid + q * THREADS;
                int g = base + row;
                if (g < E) {
                    float s = src[g], d = dest[g], a = ea[g];
                    int bi = min(max(batch[g], 0), Bm1);
                    float uu = su[bi];
                    float h[HID];
                    #pragma unroll
                    for (int j = 0; j < HID; j++) {
                        float acc = cf[(40 + j) * 2];
                        acc = fmaf(s,  cf[(j * 4 + 0) * 2], acc);
                        acc = fmaf(d,  cf[(j * 4 + 1) * 2], acc);
                        acc = fmaf(a,  cf[(j * 4 + 2) * 2], acc);
                        acc = fmaf(uu, cf[(j * 4 + 3) * 2], acc);
                        h[j] = fmaxf(acc, 0.0f);
                    }
                    #pragma unroll
                    for (int k = 0; k < NOUT; k++) {
                        float acc = cf[(240 + k) * 2];
                        #pragma unroll
                        for (int j = 0; j < HID; j++)
                            acc = fmaf(h[j], cf[(50 + k * HID + j) * 2], acc);
                        st[row * NOUT + k] = acc;
                    }
                }
            }
            __syncthreads();
            int ve = E - base; if (ve > TILE) ve = TILE;
            size_t obase = (size_t)base * NOUT;
            for (int q = tid; q < ve * NOUT; q += THREADS) out[obase + q] = st[q];
            __syncthreads();

            if (nextFull) {
                const int nbase = nextTile * TILE;
                #pragma unroll
                for (int c = 0; c < PACKS; c++) {
                    const int g0 = nbase + c * (2 * THREADS) + tid;
                    const int g1 = g0 + THREADS;
                    cs[c][0] = src[g0];  cs[c][1] = src[g1];
                    cd[c][0] = dest[g0]; cd[c][1] = dest[g1];
                    ca[c][0] = ea[g0];   ca[c][1] = ea[g1];
                    ci[c][0] = batch[g0]; ci[c][1] = batch[g1];
                }
            }
        }
        curFull = nextFull;
    }
}

extern "C" void kernel_launch(void* const* d_in, const int* in_sizes, int n_in,
                              void* d_out, int out_size)
{
    const float* src   = (const float*)d_in[0];
    const float* dest  = (const float*)d_in[1];
    const float* ea    = (const float*)d_in[2];
    const float* u     = (const float*)d_in[3];
    const int*   batch = (const int*)d_in[4];      // int32
    const float* W1    = (const float*)d_in[5];
    const float* b1    = (const float*)d_in[6];
    const float* W2    = (const float*)d_in[7];
    const float* b2    = (const float*)d_in[8];
    float* out = (float*)d_out;

    const int E = in_sizes[0];
    const int B = in_sizes[3];
    const int nTiles = (E + TILE - 1) / TILE;

    // 1) pack duplicated weight pairs into gWt (device global)
    pack_weights_kernel<<<1, 288>>>(W1, b1, W2, b2);

    // 2) D2D copy into the constant bank (capture-legal async memcpy node)
    void* gptr = nullptr;
    cudaGetSymbolAddress(&gptr, gWt);
    cudaMemcpyToSymbolAsync(cWt, gptr, NWT * sizeof(ull), 0,
                            cudaMemcpyDeviceToDevice);

    // 3) main kernel
    const int ub = (B * 4 + 15) & ~15;
    const int smemBytes = ST_BYTES + ub + 16;

    cudaFuncSetAttribute(edge_mlp_kernel,
                         cudaFuncAttributeMaxDynamicSharedMemorySize, smemBytes);

    int grid = nTiles < 296 ? nTiles : 296;   // 2 CTAs/SM resident, grid-stride
    if (grid < 1) grid = 1;

    edge_mlp_kernel<<<grid, THREADS, smemBytes>>>(
        src, dest, ea, u, batch, out, E, B, nTiles);
}